// round 15
// baseline (speedup 1.0000x reference)
#include <cuda_runtime.h>
#include <cuda_bf16.h>
#include <cstdint>

// Problem constants
#define NROWS 8192
#define DIN   1024
#define DHID  16384
#define TOPK  32
#define NCAND 48     // candidate margin for exact re-ranking
#define CAP   512    // per-row candidate list capacity

// ---------------------------------------------------------------------------
// Device scratch (static; no allocations allowed)
// ---------------------------------------------------------------------------
__device__ __nv_bfloat16 g_xhi[(size_t)NROWS * DIN];   // 16 MB
__device__ __nv_bfloat16 g_xlo[(size_t)NROWS * DIN];   // 16 MB
__device__ __nv_bfloat16 g_whi[(size_t)DHID * DIN];    // 32 MB
__device__ __nv_bfloat16 g_wlo[(size_t)DHID * DIN];    // 32 MB
__device__ float g_wdecT[(size_t)DHID * DIN];          // 64 MB
__device__ float g_tv[NROWS * TOPK];
__device__ int   g_ti[NROWS * TOPK];
__device__ float g_cv[NROWS * NCAND];
__device__ int   g_ci[NROWS * NCAND];
__device__ float g_thr[NROWS];                         // per-row threshold
__device__ float g_cdv[(size_t)NROWS * CAP];           // candidate values (16MB)
__device__ int   g_cdi[(size_t)NROWS * CAP];           // candidate indices (16MB)
__device__ int   g_ccnt[NROWS];                        // per-row candidate count
__device__ int   g_flag[NROWS];                        // fallback flags
__device__ int   g_actp[64];
__device__ float g_zfb[(size_t)NROWS * DHID];          // fallback z

// ---------------------------------------------------------------------------
// zero per-launch metadata (counters + flags)
// ---------------------------------------------------------------------------
__global__ void zero_meta_kernel(int* __restrict__ ccnt, int* __restrict__ flag)
{
    for (int i = threadIdx.x; i < NROWS; i += 256) { ccnt[i] = 0; flag[i] = 0; }
}

// ---------------------------------------------------------------------------
// fp32 -> (bf16 hi, bf16 lo) split:  hi = bf16(v), lo = bf16(v - f32(hi))
// ---------------------------------------------------------------------------
__global__ void split_kernel(const float* __restrict__ in,
                             __nv_bfloat16* __restrict__ hi,
                             __nv_bfloat16* __restrict__ lo, int n4)
{
    const int i = blockIdx.x * blockDim.x + threadIdx.x;
    if (i >= n4) return;
    const float4 v = ((const float4*)in)[i];
    float vv[4] = {v.x, v.y, v.z, v.w};
    unsigned short h[4], l[4];
#pragma unroll
    for (int j = 0; j < 4; ++j) {
        __nv_bfloat16 hb = __float2bfloat16(vv[j]);
        __nv_bfloat16 lb = __float2bfloat16(vv[j] - __bfloat162float(hb));
        h[j] = *reinterpret_cast<unsigned short*>(&hb);
        l[j] = *reinterpret_cast<unsigned short*>(&lb);
    }
    ((ushort4*)hi)[i] = make_ushort4(h[0], h[1], h[2], h[3]);
    ((ushort4*)lo)[i] = make_ushort4(l[0], l[1], l[2], l[3]);
}

// ---------------------------------------------------------------------------
// Per-row threshold: t = 2.35 * s_enc * ||x_row||  (exact conditional sigma of
// z given x; expected ~154 survivors, cap 512 = +29 sigma, floor 48 = -8.5 sigma)
// One warp per row.
// ---------------------------------------------------------------------------
__global__ void thr_kernel(const float* __restrict__ X, float* __restrict__ thr)
{
    const int lane = threadIdx.x & 31;
    const int row  = blockIdx.x * 8 + (threadIdx.x >> 5);
    const float* xr = X + (size_t)row * DIN;
    float s = 0.0f;
#pragma unroll
    for (int j = 0; j < DIN / 32; ++j) {
        const float v = xr[lane + (j << 5)];
        s += v * v;
    }
#pragma unroll
    for (int o = 16; o; o >>= 1)
        s += __shfl_xor_sync(0xFFFFFFFFu, s, o);
    if (lane == 0)
        thr[row] = 2.35f * 0.01071873f * sqrtf(s);   // 2.35 * sqrt(2/17408) * ||x||
}

// ---------------------------------------------------------------------------
// W_dec [DIN, DHID] row-major  ->  g_wdecT [DHID, DIN] row-major
// ---------------------------------------------------------------------------
__global__ void transpose_kernel(const float* __restrict__ Wd, float* __restrict__ WT)
{
    __shared__ float t[32][33];
    const int h0 = blockIdx.x << 5;
    const int i0 = blockIdx.y << 5;
    const int tx = threadIdx.x;
    const int ty = threadIdx.y;
#pragma unroll
    for (int r = 0; r < 32; r += 8)
        t[ty + r][tx] = Wd[(size_t)(i0 + ty + r) * DHID + h0 + tx];
    __syncthreads();
#pragma unroll
    for (int r = 0; r < 32; r += 8)
        WT[(size_t)(h0 + ty + r) * DIN + i0 + tx] = t[tx][ty + r];
}

// ---------------------------------------------------------------------------
// HMMA encoder: Z = relu(Xhi*Whi^T + Xhi*Wlo^T + Xlo*Whi^T)
// CTA tile 128x128 (2 CTAs/SM), 8 warps (2M x 4N), warp tile 64x32, BK=32,
// virtual K=3072, cp.async.cg 3-stage pipeline.
// Epilogue: store z AND append candidates > thr.
// ---------------------------------------------------------------------------
__device__ __forceinline__ uint32_t smem_u32(const void* p) {
    uint32_t a;
    asm("{ .reg .u64 t; cvta.to.shared.u64 t, %1; cvt.u32.u64 %0, t; }"
        : "=r"(a) : "l"(p));
    return a;
}
__device__ __forceinline__ void ldsm4(uint32_t* r, uint32_t addr) {
    asm volatile("ldmatrix.sync.aligned.m8n8.x4.shared.b16 {%0,%1,%2,%3}, [%4];\n"
        : "=r"(r[0]), "=r"(r[1]), "=r"(r[2]), "=r"(r[3]) : "r"(addr));
}
__device__ __forceinline__ void mma16816(float* c, uint32_t a0, uint32_t a1,
                                         uint32_t a2, uint32_t a3,
                                         uint32_t b0, uint32_t b1) {
    asm volatile(
        "mma.sync.aligned.m16n8k16.row.col.f32.bf16.bf16.f32 "
        "{%0,%1,%2,%3}, {%4,%5,%6,%7}, {%8,%9}, {%0,%1,%2,%3};\n"
        : "+f"(c[0]), "+f"(c[1]), "+f"(c[2]), "+f"(c[3])
        : "r"(a0), "r"(a1), "r"(a2), "r"(a3), "r"(b0), "r"(b1));
}
#define CP_ASYNC16(dst, src) \
    asm volatile("cp.async.cg.shared.global [%0], [%1], 16;\n" :: "r"(dst), "l"(src))
#define CP_COMMIT() asm volatile("cp.async.commit_group;\n" ::: "memory")
#define CP_WAIT1()  asm volatile("cp.async.wait_group 1;\n" ::: "memory")
#define CP_WAIT0()  asm volatile("cp.async.wait_group 0;\n" ::: "memory")

#define BM 128
#define BN 128
#define G_STRIDE 80                         // 64B data + 16B pad, conflict-free
#define STAGE_BYTES ((BM + BN) * G_STRIDE)  // 20480
#define G_SMEM (3 * STAGE_BYTES)            // 61440 (x2 CTAs = 120KB < 228KB)
#define NCHUNK 96                           // virtual K 3072 / 32

__device__ __forceinline__ void cand_push(float v, int row, int col,
                                          float* cdv, int* cdi, int* ccnt)
{
    const int slot = atomicAdd(&ccnt[row], 1);
    if (slot < CAP) {
        cdv[(size_t)row * CAP + slot] = v;
        cdi[(size_t)row * CAP + slot] = col;
    }
}

__global__ __launch_bounds__(256, 2) void enc_gemm_hmma(
    const __nv_bfloat16* __restrict__ Xhi, const __nv_bfloat16* __restrict__ Xlo,
    const __nv_bfloat16* __restrict__ Whi, const __nv_bfloat16* __restrict__ Wlo,
    const float* __restrict__ thr,
    float* __restrict__ Z,
    float* __restrict__ cdv, int* __restrict__ cdi, int* __restrict__ ccnt)
{
    extern __shared__ __align__(16) unsigned char sm[];
    const uint32_t sb = smem_u32(sm);

    const int tid  = threadIdx.x;
    const int lane = tid & 31;
    const int warp = tid >> 5;
    const int Mw = (warp >> 2) << 6;      // 0 / 64
    const int Nw = (warp & 3) << 5;       // 0 / 32 / 64 / 96
    const int bm = blockIdx.y << 7;
    const int bn = blockIdx.x << 7;

    const int lrow = tid >> 2;            // 0..63
    const int kc   = tid & 3;             // 16B piece in 64B row

    const int tm = (lane & 7) + ((lane >> 3) & 1) * 8;
    const int tk = lane >> 4;
    const uint32_t aOff = (Mw + tm) * G_STRIDE + tk * 16;
    const uint32_t bOff = BM * G_STRIDE + (Nw + tm) * G_STRIDE + tk * 16;

    float acc[4][4][4];
#pragma unroll
    for (int mi = 0; mi < 4; ++mi)
#pragma unroll
        for (int ni = 0; ni < 4; ++ni)
#pragma unroll
            for (int e = 0; e < 4; ++e) acc[mi][ni][e] = 0.0f;

#define ISSUE_LOAD(c, slot)                                                       \
    do {                                                                          \
        const int ph = (c) >> 5;                                                  \
        const int k0 = ((c) & 31) << 5;                                           \
        const __nv_bfloat16* Ap = (ph == 2) ? Xlo : Xhi;                          \
        const __nv_bfloat16* Bp = (ph == 1) ? Wlo : Whi;                          \
        const uint32_t base = sb + (slot) * STAGE_BYTES;                          \
        _Pragma("unroll")                                                         \
        for (int u = 0; u < 2; ++u) {                                             \
            const int r = lrow + u * 64;                                          \
            CP_ASYNC16(base + r * G_STRIDE + kc * 16,                             \
                       Ap + (size_t)(bm + r) * DIN + k0 + kc * 8);                \
        }                                                                         \
        _Pragma("unroll")                                                         \
        for (int u = 0; u < 2; ++u) {                                             \
            const int r = lrow + u * 64;                                          \
            CP_ASYNC16(base + BM * G_STRIDE + r * G_STRIDE + kc * 16,             \
                       Bp + (size_t)(bn + r) * DIN + k0 + kc * 8);                \
        }                                                                         \
    } while (0)

    ISSUE_LOAD(0, 0); CP_COMMIT();
    ISSUE_LOAD(1, 1); CP_COMMIT();

    for (int c = 0; c < NCHUNK; ++c) {
        if (c + 1 < NCHUNK) CP_WAIT1(); else CP_WAIT0();
        __syncthreads();
        if (c + 2 < NCHUNK) { ISSUE_LOAD(c + 2, (c + 2) % 3); CP_COMMIT(); }

        const uint32_t base = sb + (c % 3) * STAGE_BYTES;
#pragma unroll
        for (int ks = 0; ks < 2; ++ks) {
            uint32_t a[4][4], b[2][4];
#pragma unroll
            for (int mi = 0; mi < 4; ++mi)
                ldsm4(a[mi], base + aOff + mi * (16 * G_STRIDE) + ks * 32);
#pragma unroll
            for (int nb = 0; nb < 2; ++nb)
                ldsm4(b[nb], base + bOff + nb * (16 * G_STRIDE) + ks * 32);
#pragma unroll
            for (int mi = 0; mi < 4; ++mi)
#pragma unroll
                for (int nb = 0; nb < 2; ++nb) {
                    mma16816(acc[mi][2 * nb],     a[mi][0], a[mi][1], a[mi][2], a[mi][3],
                             b[nb][0], b[nb][2]);
                    mma16816(acc[mi][2 * nb + 1], a[mi][0], a[mi][1], a[mi][2], a[mi][3],
                             b[nb][1], b[nb][3]);
                }
        }
    }
#undef ISSUE_LOAD

    // epilogue: relu + store z + candidate filter (z > per-row threshold)
    const int er = lane >> 2;
    const int ec = (lane & 3) << 1;
#pragma unroll
    for (int mi = 0; mi < 4; ++mi) {
        const int r0 = bm + Mw + mi * 16 + er;
        const int r1 = r0 + 8;
        const float t0 = thr[r0];
        const float t1 = thr[r1];
        float* z0 = Z + (size_t)r0 * DHID + bn + Nw + ec;
        float* z1 = Z + (size_t)r1 * DHID + bn + Nw + ec;
#pragma unroll
        for (int ni = 0; ni < 4; ++ni) {
            const int col = bn + Nw + ni * 8 + ec;
            float2 v0, v1;
            v0.x = fmaxf(acc[mi][ni][0], 0.0f);
            v0.y = fmaxf(acc[mi][ni][1], 0.0f);
            v1.x = fmaxf(acc[mi][ni][2], 0.0f);
            v1.y = fmaxf(acc[mi][ni][3], 0.0f);
            *(float2*)(z0 + ni * 8) = v0;
            *(float2*)(z1 + ni * 8) = v1;
            if (v0.x > t0) cand_push(v0.x, r0, col,     cdv, cdi, ccnt);
            if (v0.y > t0) cand_push(v0.y, r0, col + 1, cdv, cdi, ccnt);
            if (v1.x > t1) cand_push(v1.x, r1, col,     cdv, cdi, ccnt);
            if (v1.y > t1) cand_push(v1.y, r1, col + 1, cdv, cdi, ccnt);
        }
    }
}

// ---------------------------------------------------------------------------
// zsp zero-fill (pure streaming write)
// ---------------------------------------------------------------------------
__global__ void zsp_zero_kernel(float4* __restrict__ zo)
{
    const size_t i = (size_t)blockIdx.x * 256 + threadIdx.x;
    zo[i] = make_float4(0.f, 0.f, 0.f, 0.f);
}

// ---------------------------------------------------------------------------
// Rank-select exact top-NCAND (by z~, tie-break lower idx) among the row's
// candidates. Order-invariant wrt append order -> deterministic. Rows whose
// count left [NCAND, CAP] get flagged for the fallback path.
// ---------------------------------------------------------------------------
__global__ __launch_bounds__(256) void rank_kernel(
    const float* __restrict__ cdv, const int* __restrict__ cdi,
    const int* __restrict__ ccnt, int* __restrict__ flag,
    float* __restrict__ cvg, int* __restrict__ cig)
{
    __shared__ float sv[CAP];
    __shared__ int   si_[CAP];
    const int row = blockIdx.x;
    const int tid = threadIdx.x;
    const int cnt = ccnt[row];

    if (cnt < NCAND || cnt > CAP) {
        if (tid == 0) flag[row] = 1;
        return;
    }
    for (int i = tid; i < cnt; i += 256) {
        sv[i]  = cdv[(size_t)row * CAP + i];
        si_[i] = cdi[(size_t)row * CAP + i];
    }
    __syncthreads();

    for (int i = tid; i < cnt; i += 256) {
        const float v = sv[i];
        const int   ii = si_[i];
        int rank = 0;
        for (int j = 0; j < cnt; ++j) {
            const float u = sv[j];
            if (u > v || (u == v && si_[j] < ii)) ++rank;
        }
        if (rank < NCAND) {
            cvg[row * NCAND + rank] = v;
            cig[row * NCAND + rank] = ii;
        }
    }
}

// ---------------------------------------------------------------------------
// Fallback: full-row serial top-NCAND for flagged rows (should ~never run).
// ---------------------------------------------------------------------------
__global__ __launch_bounds__(256) void fallback_kernel(
    const float* __restrict__ Z, const int* __restrict__ flag,
    float* __restrict__ cvg, int* __restrict__ cig)
{
    if (!flag[blockIdx.x]) return;

    extern __shared__ float s[];
    __shared__ float wv[8];
    __shared__ int   wi[8];

    const int tid = threadIdx.x;
    const size_t rowoff = (size_t)blockIdx.x * DHID;
    const float4* zr = (const float4*)(Z + rowoff);
    float4* sv4 = (float4*)s;
#pragma unroll
    for (int j = 0; j < 16; ++j)
        sv4[j * 256 + tid] = zr[j * 256 + tid];
    __syncthreads();

    float lv = -1.0f; int li = tid;
#pragma unroll 8
    for (int j = 0; j < 64; ++j) {
        const int idx = tid + (j << 8);
        const float v = s[idx];
        if (v > lv) { lv = v; li = idx; }
    }
    for (int it = 0; it < NCAND; ++it) {
        float v = lv; int i = li;
#pragma unroll
        for (int o = 16; o; o >>= 1) {
            const float v2 = __shfl_down_sync(0xFFFFFFFFu, v, o);
            const int   i2 = __shfl_down_sync(0xFFFFFFFFu, i, o);
            if (v2 > v || (v2 == v && i2 < i)) { v = v2; i = i2; }
        }
        if ((tid & 31) == 0) { wv[tid >> 5] = v; wi[tid >> 5] = i; }
        __syncthreads();
        float bv = wv[0]; int bi = wi[0];
#pragma unroll
        for (int w = 1; w < 8; ++w) {
            const float v2 = wv[w]; const int i2 = wi[w];
            if (v2 > bv || (v2 == bv && i2 < bi)) { bv = v2; bi = i2; }
        }
        if (tid == 0) {
            cvg[blockIdx.x * NCAND + it] = bv;
            cig[blockIdx.x * NCAND + it] = bi;
        }
        if ((bi & 255) == tid) {
            s[bi] = -1.0f;
            lv = -1.0f; li = tid;
#pragma unroll 8
            for (int j = 0; j < 64; ++j) {
                const int idx = tid + (j << 8);
                const float vv = s[idx];
                if (vv > lv) { lv = vv; li = idx; }
            }
        }
        __syncthreads();
    }
}

// ---------------------------------------------------------------------------
// Exact re-rank: recompute the NCAND candidate dot products per row in fp64,
// select the true top-TOPK, write (val, idx) and scatter z_sparse.
// ---------------------------------------------------------------------------
__global__ __launch_bounds__(256) void refine_kernel(const float* __restrict__ X,
                                                     const float* __restrict__ W,
                                                     const float* __restrict__ cvg,
                                                     const int* __restrict__ cig,
                                                     float* __restrict__ Zsp,
                                                     float* __restrict__ tvg,
                                                     int* __restrict__ tig,
                                                     int write_zsp)
{
    __shared__ float  sx[DIN];
    __shared__ double dres[NCAND];
    __shared__ float  scv[NCAND];
    __shared__ int    sci[NCAND];

    const int tid  = threadIdx.x;
    const int row  = blockIdx.x;
    const int lane = tid & 31;
    const int w    = tid >> 5;

    for (int j = tid; j < DIN; j += 256)
        sx[j] = X[(size_t)row * DIN + j];
    if (tid < NCAND) {
        scv[tid] = cvg[row * NCAND + tid];
        sci[tid] = cig[row * NCAND + tid];
    }
    __syncthreads();

    for (int c = w; c < NCAND; c += 8) {
        const float* wr = W + ((size_t)sci[c] << 10);
        double a0 = 0.0, a1 = 0.0;
#pragma unroll
        for (int j = 0; j < DIN / 64; ++j) {
            const int e = lane + (j << 6);
            a0 += (double)sx[e]      * (double)wr[e];
            a1 += (double)sx[e + 32] * (double)wr[e + 32];
        }
        double acc = a0 + a1;
#pragma unroll
        for (int o = 16; o; o >>= 1)
            acc += __shfl_down_sync(0xFFFFFFFFu, acc, o);
        if (lane == 0) dres[c] = acc;
    }
    __syncthreads();

    if (tid < NCAND) {
        const double v = dres[tid];
        int rank = 0;
#pragma unroll 8
        for (int j = 0; j < NCAND; ++j) {
            const double u = dres[j];
            if (u > v || (u == v && j < tid)) ++rank;
        }
        if (rank < TOPK) {
            tvg[row * TOPK + rank] = scv[tid];
            tig[row * TOPK + rank] = sci[tid];
            if (write_zsp)
                Zsp[(size_t)row * DHID + sci[tid]] = scv[tid];
        }
    }
}

// ---------------------------------------------------------------------------
// Decoder: x_hat[n,:] = sum_k tv[n,k] * WdT[ti[n,k], :]   (one CTA per row)
// ---------------------------------------------------------------------------
__global__ __launch_bounds__(256) void dec_kernel(const float* __restrict__ WT,
                                                  const float* __restrict__ tvg,
                                                  const int* __restrict__ tig,
                                                  float* __restrict__ xhat)
{
    __shared__ float sv[TOPK];
    __shared__ int   si[TOPK];
    const int tid = threadIdx.x;
    const int row = blockIdx.x;
    if (tid < TOPK) {
        sv[tid] = tvg[row * TOPK + tid];
        si[tid] = tig[row * TOPK + tid];
    }
    __syncthreads();

    const int c = tid << 2;
    float4 acc = make_float4(0.f, 0.f, 0.f, 0.f);
#pragma unroll
    for (int k = 0; k < TOPK; ++k) {
        const float v = sv[k];
        const float4 w = *(const float4*)(WT + ((size_t)si[k] << 10) + c);
        acc.x += v * w.x; acc.y += v * w.y;
        acc.z += v * w.z; acc.w += v * w.w;
    }
    *(float4*)(xhat + ((size_t)row << 10) + c) = acc;
}

// ---------------------------------------------------------------------------
// active = mean_n ( count_k(top-k val > 0) ) — parallel deterministic version
// ---------------------------------------------------------------------------
__global__ void active_part(const float* __restrict__ tvg, int* __restrict__ part)
{
    __shared__ int sc[256];
    const int tid = threadIdx.x;
    int c = 0;
    for (int i = blockIdx.x * 256 + tid; i < NROWS * TOPK; i += 64 * 256)
        c += (tvg[i] > 0.0f) ? 1 : 0;
    sc[tid] = c;
    __syncthreads();
    for (int o = 128; o; o >>= 1) {
        if (tid < o) sc[tid] += sc[tid + o];
        __syncthreads();
    }
    if (tid == 0) part[blockIdx.x] = sc[0];
}

__global__ void active_fin(const int* __restrict__ part, float* __restrict__ act)
{
    if (threadIdx.x == 0) {
        int s = 0;
#pragma unroll
        for (int i = 0; i < 64; ++i) s += part[i];
        act[0] = (float)s / (float)NROWS;
    }
}

// ---------------------------------------------------------------------------
// Launch
// ---------------------------------------------------------------------------
extern "C" void kernel_launch(void* const* d_in, const int* in_sizes, int n_in,
                              void* d_out, int out_size)
{
    (void)in_sizes; (void)n_in;
    const float* x  = (const float*)d_in[0];
    const float* We = (const float*)d_in[1];
    const float* Wd = (const float*)d_in[2];
    float* out = (float*)d_out;

    __nv_bfloat16 *g_xh, *g_xl, *g_wh, *g_wl;
    cudaGetSymbolAddress((void**)&g_xh, g_xhi);
    cudaGetSymbolAddress((void**)&g_xl, g_xlo);
    cudaGetSymbolAddress((void**)&g_wh, g_whi);
    cudaGetSymbolAddress((void**)&g_wl, g_wlo);
    float* g_wt;  cudaGetSymbolAddress((void**)&g_wt,  g_wdecT);
    float* g_tvp; cudaGetSymbolAddress((void**)&g_tvp, g_tv);
    int*   g_tip; cudaGetSymbolAddress((void**)&g_tip, g_ti);
    float* g_cvp; cudaGetSymbolAddress((void**)&g_cvp, g_cv);
    int*   g_cip; cudaGetSymbolAddress((void**)&g_cip, g_ci);
    float* g_thp; cudaGetSymbolAddress((void**)&g_thp, g_thr);
    float* g_cdvp; cudaGetSymbolAddress((void**)&g_cdvp, g_cdv);
    int*   g_cdip; cudaGetSymbolAddress((void**)&g_cdip, g_cdi);
    int*   g_ccp; cudaGetSymbolAddress((void**)&g_ccp, g_ccnt);
    int*   g_flp; cudaGetSymbolAddress((void**)&g_flp, g_flag);
    int*   g_app; cudaGetSymbolAddress((void**)&g_app, g_actp);
    float* g_zp;  cudaGetSymbolAddress((void**)&g_zp,  g_zfb);

    const long long XH = (long long)NROWS * DIN;        // 8388608
    const long long ZZ = (long long)NROWS * DHID;       // 134217728
    const long long os = (long long)out_size;

    // Output layout: [x_hat | z_sparse | z | active] flat concat.
    float* xhat = out;
    float* zsp  = nullptr;
    float* z    = nullptr;
    float* act  = nullptr;
    if (os >= XH + 2 * ZZ) {
        zsp = out + XH;
        z   = out + XH + ZZ;
        if (os > XH + 2 * ZZ) act = out + XH + 2 * ZZ;
    } else if (os >= XH + ZZ) {
        zsp = out + XH;
    }
    if (!z) z = g_zp;

    cudaFuncSetAttribute(enc_gemm_hmma,
                         cudaFuncAttributeMaxDynamicSharedMemorySize, G_SMEM);
    cudaFuncSetAttribute(fallback_kernel,
                         cudaFuncAttributeMaxDynamicSharedMemorySize, DHID * 4);

    // 0. zero per-launch metadata (counters + flags)
    zero_meta_kernel<<<1, 256>>>(g_ccp, g_flp);

    // 1. bf16 hi/lo splits of X and W_enc; per-row thresholds
    split_kernel<<<(NROWS * DIN / 4 + 255) / 256, 256>>>(x, g_xh, g_xl, NROWS * DIN / 4);
    split_kernel<<<(DHID * DIN / 4 + 255) / 256, 256>>>(We, g_wh, g_wl, DHID * DIN / 4);
    thr_kernel<<<NROWS / 8, 256>>>(x, g_thp);

    // 2. transpose W_dec (independent; needed by decoder)
    transpose_kernel<<<dim3(DHID / 32, DIN / 32), dim3(32, 8)>>>(Wd, g_wt);

    // 3. HMMA encoder GEMM + relu -> z, with fused candidate filter (2 CTAs/SM)
    enc_gemm_hmma<<<dim3(DHID / BN, NROWS / BM), 256, G_SMEM>>>(
        g_xh, g_xl, g_wh, g_wl, g_thp, z, g_cdvp, g_cdip, g_ccp);

    // 4. zero-fill z_sparse (scatter happens in refine)
    if (zsp)
        zsp_zero_kernel<<<(int)(ZZ / 4 / 256), 256>>>((float4*)zsp);

    // 5. exact top-NCAND among filtered candidates; flag anomalies
    rank_kernel<<<NROWS, 256>>>(g_cdvp, g_cdip, g_ccp, g_flp, g_cvp, g_cip);

    // 6. fallback full-row scan for flagged rows (normally instant no-op)
    fallback_kernel<<<NROWS, 256, DHID * 4>>>(z, g_flp, g_cvp, g_cip);

    // 7. exact fp64 re-rank of candidates -> true top-32, scatter z_sparse
    refine_kernel<<<NROWS, 256>>>(x, We, g_cvp, g_cip,
                                  zsp ? zsp : z, g_tvp, g_tip,
                                  zsp != nullptr ? 1 : 0);

    // 8. sparse decoder -> x_hat
    dec_kernel<<<NROWS, 256>>>(g_wt, g_tvp, g_tip, xhat);

    // 9. active scalar (parallel, deterministic int counts)
    if (act) {
        active_part<<<64, 256>>>(g_tvp, g_app);
        active_fin<<<1, 32>>>(g_app, act);
    }
}

// round 16
// speedup vs baseline: 1.7849x; 1.7849x over previous
#include <cuda_runtime.h>
#include <cuda_fp16.h>
#include <cstdint>

// Problem constants
#define NROWS 8192
#define DIN   1024
#define DHID  16384
#define TOPK  32
#define NCAND 48     // candidate margin for exact re-ranking
#define CAP   512    // per-row candidate list capacity

// ---------------------------------------------------------------------------
// Device scratch (static; no allocations allowed)
// ---------------------------------------------------------------------------
__device__ __half g_xhi[(size_t)NROWS * DIN];          // 16 MB (fp16 hi of x)
__device__ __half g_whi[(size_t)DHID * DIN];           // 32 MB (fp16 hi of W_enc)
__device__ __half g_wlo[(size_t)DHID * DIN];           // 32 MB (fp16 lo of W_enc)
__device__ float g_wdecT[(size_t)DHID * DIN];          // 64 MB
__device__ float g_tv[NROWS * TOPK];
__device__ int   g_ti[NROWS * TOPK];
__device__ float g_cv[NROWS * NCAND];
__device__ int   g_ci[NROWS * NCAND];
__device__ float g_thr[NROWS];                         // per-row threshold
__device__ float g_cdv[(size_t)NROWS * CAP];           // candidate values (16MB)
__device__ int   g_cdi[(size_t)NROWS * CAP];           // candidate indices (16MB)
__device__ int   g_ccnt[NROWS];                        // per-row candidate count
__device__ int   g_flag[NROWS];                        // fallback flags
__device__ int   g_actp[64];
__device__ float g_zfb[(size_t)NROWS * DHID];          // fallback z

// ---------------------------------------------------------------------------
// zero per-launch metadata (counters + flags)
// ---------------------------------------------------------------------------
__global__ void zero_meta_kernel(int* __restrict__ ccnt, int* __restrict__ flag)
{
    for (int i = threadIdx.x; i < NROWS; i += 256) { ccnt[i] = 0; flag[i] = 0; }
}

// ---------------------------------------------------------------------------
// fp32 -> fp16 hi only (for X; the dropped Xlo term is the 2-pass residual)
// ---------------------------------------------------------------------------
__global__ void splitx_kernel(const float* __restrict__ in,
                              __half* __restrict__ hi, int n4)
{
    const int i = blockIdx.x * blockDim.x + threadIdx.x;
    if (i >= n4) return;
    const float4 v = ((const float4*)in)[i];
    __half2 h0 = make_half2(__float2half_rn(v.x), __float2half_rn(v.y));
    __half2 h1 = make_half2(__float2half_rn(v.z), __float2half_rn(v.w));
    ((__half2*)hi)[2 * i]     = h0;
    ((__half2*)hi)[2 * i + 1] = h1;
}

// ---------------------------------------------------------------------------
// fp32 -> (fp16 hi, fp16 lo):  hi = h(v), lo = h(v - f32(hi))
// ---------------------------------------------------------------------------
__global__ void splitw_kernel(const float* __restrict__ in,
                              __half* __restrict__ hi,
                              __half* __restrict__ lo, int n4)
{
    const int i = blockIdx.x * blockDim.x + threadIdx.x;
    if (i >= n4) return;
    const float4 v = ((const float4*)in)[i];
    float vv[4] = {v.x, v.y, v.z, v.w};
    __half h[4], l[4];
#pragma unroll
    for (int j = 0; j < 4; ++j) {
        h[j] = __float2half_rn(vv[j]);
        l[j] = __float2half_rn(vv[j] - __half2float(h[j]));
    }
    ((__half2*)hi)[2 * i]     = make_half2(h[0], h[1]);
    ((__half2*)hi)[2 * i + 1] = make_half2(h[2], h[3]);
    ((__half2*)lo)[2 * i]     = make_half2(l[0], l[1]);
    ((__half2*)lo)[2 * i + 1] = make_half2(l[2], l[3]);
}

// ---------------------------------------------------------------------------
// Per-row threshold: t = 2.35 * s_enc * ||x_row||
// ---------------------------------------------------------------------------
__global__ void thr_kernel(const float* __restrict__ X, float* __restrict__ thr)
{
    const int lane = threadIdx.x & 31;
    const int row  = blockIdx.x * 8 + (threadIdx.x >> 5);
    const float* xr = X + (size_t)row * DIN;
    float s = 0.0f;
#pragma unroll
    for (int j = 0; j < DIN / 32; ++j) {
        const float v = xr[lane + (j << 5)];
        s += v * v;
    }
#pragma unroll
    for (int o = 16; o; o >>= 1)
        s += __shfl_xor_sync(0xFFFFFFFFu, s, o);
    if (lane == 0)
        thr[row] = 2.35f * 0.01071873f * sqrtf(s);
}

// ---------------------------------------------------------------------------
// W_dec [DIN, DHID] row-major  ->  g_wdecT [DHID, DIN] row-major
// ---------------------------------------------------------------------------
__global__ void transpose_kernel(const float* __restrict__ Wd, float* __restrict__ WT)
{
    __shared__ float t[32][33];
    const int h0 = blockIdx.x << 5;
    const int i0 = blockIdx.y << 5;
    const int tx = threadIdx.x;
    const int ty = threadIdx.y;
#pragma unroll
    for (int r = 0; r < 32; r += 8)
        t[ty + r][tx] = Wd[(size_t)(i0 + ty + r) * DHID + h0 + tx];
    __syncthreads();
#pragma unroll
    for (int r = 0; r < 32; r += 8)
        WT[(size_t)(h0 + ty + r) * DIN + i0 + tx] = t[tx][ty + r];
}

// ---------------------------------------------------------------------------
// HMMA encoder (R14 structure): Z = relu( Xhi*Whi^T + Xhi*Wlo^T )  [fp16 2-pass]
// CTA tile 128x256, 8 warps (2M x 4N), warp tile 64x64, BK=32, virtual K=2048,
// cp.async.cg 3-stage pipeline. Epilogue: store z AND append candidates > thr.
// ---------------------------------------------------------------------------
__device__ __forceinline__ uint32_t smem_u32(const void* p) {
    uint32_t a;
    asm("{ .reg .u64 t; cvta.to.shared.u64 t, %1; cvt.u32.u64 %0, t; }"
        : "=r"(a) : "l"(p));
    return a;
}
__device__ __forceinline__ void ldsm4(uint32_t* r, uint32_t addr) {
    asm volatile("ldmatrix.sync.aligned.m8n8.x4.shared.b16 {%0,%1,%2,%3}, [%4];\n"
        : "=r"(r[0]), "=r"(r[1]), "=r"(r[2]), "=r"(r[3]) : "r"(addr));
}
__device__ __forceinline__ void mma16816(float* c, uint32_t a0, uint32_t a1,
                                         uint32_t a2, uint32_t a3,
                                         uint32_t b0, uint32_t b1) {
    asm volatile(
        "mma.sync.aligned.m16n8k16.row.col.f32.f16.f16.f32 "
        "{%0,%1,%2,%3}, {%4,%5,%6,%7}, {%8,%9}, {%0,%1,%2,%3};\n"
        : "+f"(c[0]), "+f"(c[1]), "+f"(c[2]), "+f"(c[3])
        : "r"(a0), "r"(a1), "r"(a2), "r"(a3), "r"(b0), "r"(b1));
}
#define CP_ASYNC16(dst, src) \
    asm volatile("cp.async.cg.shared.global [%0], [%1], 16;\n" :: "r"(dst), "l"(src))
#define CP_COMMIT() asm volatile("cp.async.commit_group;\n" ::: "memory")
#define CP_WAIT1()  asm volatile("cp.async.wait_group 1;\n" ::: "memory")
#define CP_WAIT0()  asm volatile("cp.async.wait_group 0;\n" ::: "memory")

#define BM 128
#define BN 256
#define G_STRIDE 80                         // 64B data + 16B pad, conflict-free
#define STAGE_BYTES ((BM + BN) * G_STRIDE)  // 30720
#define G_SMEM (3 * STAGE_BYTES)            // 92160
#define NCHUNK 64                           // virtual K 2048 / 32

__device__ __forceinline__ void cand_push(float v, int row, int col,
                                          float* cdv, int* cdi, int* ccnt)
{
    const int slot = atomicAdd(&ccnt[row], 1);
    if (slot < CAP) {
        cdv[(size_t)row * CAP + slot] = v;
        cdi[(size_t)row * CAP + slot] = col;
    }
}

__global__ __launch_bounds__(256, 1) void enc_gemm_hmma(
    const __half* __restrict__ Xhi,
    const __half* __restrict__ Whi, const __half* __restrict__ Wlo,
    const float* __restrict__ thr,
    float* __restrict__ Z,
    float* __restrict__ cdv, int* __restrict__ cdi, int* __restrict__ ccnt)
{
    extern __shared__ __align__(16) unsigned char sm[];
    const uint32_t sb = smem_u32(sm);

    const int tid  = threadIdx.x;
    const int lane = tid & 31;
    const int warp = tid >> 5;
    const int Mw = (warp >> 2) << 6;      // 0 / 64
    const int Nw = (warp & 3) << 6;       // 0 / 64 / 128 / 192
    const int bm = blockIdx.y << 7;
    const int bn = blockIdx.x << 8;

    const int lrow = tid >> 2;            // 0..63
    const int kc   = tid & 3;             // 16B piece in 64B row

    const int tm = (lane & 7) + ((lane >> 3) & 1) * 8;
    const int tk = lane >> 4;
    const uint32_t aOff = (Mw + tm) * G_STRIDE + tk * 16;
    const uint32_t bOff = BM * G_STRIDE + (Nw + tm) * G_STRIDE + tk * 16;

    float acc[4][8][4];
#pragma unroll
    for (int mi = 0; mi < 4; ++mi)
#pragma unroll
        for (int ni = 0; ni < 8; ++ni)
#pragma unroll
            for (int e = 0; e < 4; ++e) acc[mi][ni][e] = 0.0f;

#define ISSUE_LOAD(c, slot)                                                       \
    do {                                                                          \
        const int ph = (c) >> 5;                                                  \
        const int k0 = ((c) & 31) << 5;                                           \
        const __half* Bp = ph ? Wlo : Whi;                                        \
        const uint32_t base = sb + (slot) * STAGE_BYTES;                          \
        _Pragma("unroll")                                                         \
        for (int u = 0; u < 2; ++u) {                                             \
            const int r = lrow + u * 64;                                          \
            CP_ASYNC16(base + r * G_STRIDE + kc * 16,                             \
                       Xhi + (size_t)(bm + r) * DIN + k0 + kc * 8);               \
        }                                                                         \
        _Pragma("unroll")                                                         \
        for (int u = 0; u < 4; ++u) {                                             \
            const int r = lrow + u * 64;                                          \
            CP_ASYNC16(base + BM * G_STRIDE + r * G_STRIDE + kc * 16,             \
                       Bp + (size_t)(bn + r) * DIN + k0 + kc * 8);                \
        }                                                                         \
    } while (0)

    ISSUE_LOAD(0, 0); CP_COMMIT();
    ISSUE_LOAD(1, 1); CP_COMMIT();

    for (int c = 0; c < NCHUNK; ++c) {
        if (c + 1 < NCHUNK) CP_WAIT1(); else CP_WAIT0();
        __syncthreads();
        if (c + 2 < NCHUNK) { ISSUE_LOAD(c + 2, (c + 2) % 3); CP_COMMIT(); }

        const uint32_t base = sb + (c % 3) * STAGE_BYTES;
#pragma unroll
        for (int ks = 0; ks < 2; ++ks) {
            uint32_t a[4][4], b[4][4];
#pragma unroll
            for (int mi = 0; mi < 4; ++mi)
                ldsm4(a[mi], base + aOff + mi * (16 * G_STRIDE) + ks * 32);
#pragma unroll
            for (int nb = 0; nb < 4; ++nb)
                ldsm4(b[nb], base + bOff + nb * (16 * G_STRIDE) + ks * 32);
#pragma unroll
            for (int mi = 0; mi < 4; ++mi)
#pragma unroll
                for (int nb = 0; nb < 4; ++nb) {
                    mma16816(acc[mi][2 * nb],     a[mi][0], a[mi][1], a[mi][2], a[mi][3],
                             b[nb][0], b[nb][2]);
                    mma16816(acc[mi][2 * nb + 1], a[mi][0], a[mi][1], a[mi][2], a[mi][3],
                             b[nb][1], b[nb][3]);
                }
        }
    }
#undef ISSUE_LOAD

    // epilogue: relu + store z + candidate filter (z > per-row threshold)
    const int er = lane >> 2;
    const int ec = (lane & 3) << 1;
#pragma unroll
    for (int mi = 0; mi < 4; ++mi) {
        const int r0 = bm + Mw + mi * 16 + er;
        const int r1 = r0 + 8;
        const float t0 = thr[r0];
        const float t1 = thr[r1];
        float* z0 = Z + (size_t)r0 * DHID + bn + Nw + ec;
        float* z1 = Z + (size_t)r1 * DHID + bn + Nw + ec;
#pragma unroll
        for (int ni = 0; ni < 8; ++ni) {
            const int col = bn + Nw + ni * 8 + ec;
            float2 v0, v1;
            v0.x = fmaxf(acc[mi][ni][0], 0.0f);
            v0.y = fmaxf(acc[mi][ni][1], 0.0f);
            v1.x = fmaxf(acc[mi][ni][2], 0.0f);
            v1.y = fmaxf(acc[mi][ni][3], 0.0f);
            *(float2*)(z0 + ni * 8) = v0;
            *(float2*)(z1 + ni * 8) = v1;
            if (v0.x > t0) cand_push(v0.x, r0, col,     cdv, cdi, ccnt);
            if (v0.y > t0) cand_push(v0.y, r0, col + 1, cdv, cdi, ccnt);
            if (v1.x > t1) cand_push(v1.x, r1, col,     cdv, cdi, ccnt);
            if (v1.y > t1) cand_push(v1.y, r1, col + 1, cdv, cdi, ccnt);
        }
    }
}

// ---------------------------------------------------------------------------
// zsp zero-fill (pure streaming write)
// ---------------------------------------------------------------------------
__global__ void zsp_zero_kernel(float4* __restrict__ zo)
{
    const size_t i = (size_t)blockIdx.x * 256 + threadIdx.x;
    zo[i] = make_float4(0.f, 0.f, 0.f, 0.f);
}

// ---------------------------------------------------------------------------
// Rank-select exact top-NCAND among the row's candidates (deterministic).
// Rows whose count left [NCAND, CAP] get flagged for the fallback path.
// ---------------------------------------------------------------------------
__global__ __launch_bounds__(256) void rank_kernel(
    const float* __restrict__ cdv, const int* __restrict__ cdi,
    const int* __restrict__ ccnt, int* __restrict__ flag,
    float* __restrict__ cvg, int* __restrict__ cig)
{
    __shared__ float sv[CAP];
    __shared__ int   si_[CAP];
    const int row = blockIdx.x;
    const int tid = threadIdx.x;
    const int cnt = ccnt[row];

    if (cnt < NCAND || cnt > CAP) {
        if (tid == 0) flag[row] = 1;
        return;
    }
    for (int i = tid; i < cnt; i += 256) {
        sv[i]  = cdv[(size_t)row * CAP + i];
        si_[i] = cdi[(size_t)row * CAP + i];
    }
    __syncthreads();

    for (int i = tid; i < cnt; i += 256) {
        const float v = sv[i];
        const int   ii = si_[i];
        int rank = 0;
        for (int j = 0; j < cnt; ++j) {
            const float u = sv[j];
            if (u > v || (u == v && si_[j] < ii)) ++rank;
        }
        if (rank < NCAND) {
            cvg[row * NCAND + rank] = v;
            cig[row * NCAND + rank] = ii;
        }
    }
}

// ---------------------------------------------------------------------------
// Fallback: full-row serial top-NCAND for flagged rows (should ~never run).
// ---------------------------------------------------------------------------
__global__ __launch_bounds__(256) void fallback_kernel(
    const float* __restrict__ Z, const int* __restrict__ flag,
    float* __restrict__ cvg, int* __restrict__ cig)
{
    if (!flag[blockIdx.x]) return;

    extern __shared__ float s[];
    __shared__ float wv[8];
    __shared__ int   wi[8];

    const int tid = threadIdx.x;
    const size_t rowoff = (size_t)blockIdx.x * DHID;
    const float4* zr = (const float4*)(Z + rowoff);
    float4* sv4 = (float4*)s;
#pragma unroll
    for (int j = 0; j < 16; ++j)
        sv4[j * 256 + tid] = zr[j * 256 + tid];
    __syncthreads();

    float lv = -1.0f; int li = tid;
#pragma unroll 8
    for (int j = 0; j < 64; ++j) {
        const int idx = tid + (j << 8);
        const float v = s[idx];
        if (v > lv) { lv = v; li = idx; }
    }
    for (int it = 0; it < NCAND; ++it) {
        float v = lv; int i = li;
#pragma unroll
        for (int o = 16; o; o >>= 1) {
            const float v2 = __shfl_down_sync(0xFFFFFFFFu, v, o);
            const int   i2 = __shfl_down_sync(0xFFFFFFFFu, i, o);
            if (v2 > v || (v2 == v && i2 < i)) { v = v2; i = i2; }
        }
        if ((tid & 31) == 0) { wv[tid >> 5] = v; wi[tid >> 5] = i; }
        __syncthreads();
        float bv = wv[0]; int bi = wi[0];
#pragma unroll
        for (int w = 1; w < 8; ++w) {
            const float v2 = wv[w]; const int i2 = wi[w];
            if (v2 > bv || (v2 == bv && i2 < bi)) { bv = v2; bi = i2; }
        }
        if (tid == 0) {
            cvg[blockIdx.x * NCAND + it] = bv;
            cig[blockIdx.x * NCAND + it] = bi;
        }
        if ((bi & 255) == tid) {
            s[bi] = -1.0f;
            lv = -1.0f; li = tid;
#pragma unroll 8
            for (int j = 0; j < 64; ++j) {
                const int idx = tid + (j << 8);
                const float vv = s[idx];
                if (vv > lv) { lv = vv; li = idx; }
            }
        }
        __syncthreads();
    }
}

// ---------------------------------------------------------------------------
// Exact re-rank: recompute the NCAND candidate dot products per row in fp64,
// select the true top-TOPK, write (val, idx) and scatter z_sparse.
// ---------------------------------------------------------------------------
__global__ __launch_bounds__(256) void refine_kernel(const float* __restrict__ X,
                                                     const float* __restrict__ W,
                                                     const float* __restrict__ cvg,
                                                     const int* __restrict__ cig,
                                                     float* __restrict__ Zsp,
                                                     float* __restrict__ tvg,
                                                     int* __restrict__ tig,
                                                     int write_zsp)
{
    __shared__ float  sx[DIN];
    __shared__ double dres[NCAND];
    __shared__ float  scv[NCAND];
    __shared__ int    sci[NCAND];

    const int tid  = threadIdx.x;
    const int row  = blockIdx.x;
    const int lane = tid & 31;
    const int w    = tid >> 5;

    for (int j = tid; j < DIN; j += 256)
        sx[j] = X[(size_t)row * DIN + j];
    if (tid < NCAND) {
        scv[tid] = cvg[row * NCAND + tid];
        sci[tid] = cig[row * NCAND + tid];
    }
    __syncthreads();

    for (int c = w; c < NCAND; c += 8) {
        const float* wr = W + ((size_t)sci[c] << 10);
        double a0 = 0.0, a1 = 0.0;
#pragma unroll
        for (int j = 0; j < DIN / 64; ++j) {
            const int e = lane + (j << 6);
            a0 += (double)sx[e]      * (double)wr[e];
            a1 += (double)sx[e + 32] * (double)wr[e + 32];
        }
        double acc = a0 + a1;
#pragma unroll
        for (int o = 16; o; o >>= 1)
            acc += __shfl_down_sync(0xFFFFFFFFu, acc, o);
        if (lane == 0) dres[c] = acc;
    }
    __syncthreads();

    if (tid < NCAND) {
        const double v = dres[tid];
        int rank = 0;
#pragma unroll 8
        for (int j = 0; j < NCAND; ++j) {
            const double u = dres[j];
            if (u > v || (u == v && j < tid)) ++rank;
        }
        if (rank < TOPK) {
            tvg[row * TOPK + rank] = scv[tid];
            tig[row * TOPK + rank] = sci[tid];
            if (write_zsp)
                Zsp[(size_t)row * DHID + sci[tid]] = scv[tid];
        }
    }
}

// ---------------------------------------------------------------------------
// Decoder: x_hat[n,:] = sum_k tv[n,k] * WdT[ti[n,k], :]   (one CTA per row)
// ---------------------------------------------------------------------------
__global__ __launch_bounds__(256) void dec_kernel(const float* __restrict__ WT,
                                                  const float* __restrict__ tvg,
                                                  const int* __restrict__ tig,
                                                  float* __restrict__ xhat)
{
    __shared__ float sv[TOPK];
    __shared__ int   si[TOPK];
    const int tid = threadIdx.x;
    const int row = blockIdx.x;
    if (tid < TOPK) {
        sv[tid] = tvg[row * TOPK + tid];
        si[tid] = tig[row * TOPK + tid];
    }
    __syncthreads();

    const int c = tid << 2;
    float4 acc = make_float4(0.f, 0.f, 0.f, 0.f);
#pragma unroll
    for (int k = 0; k < TOPK; ++k) {
        const float v = sv[k];
        const float4 w = *(const float4*)(WT + ((size_t)si[k] << 10) + c);
        acc.x += v * w.x; acc.y += v * w.y;
        acc.z += v * w.z; acc.w += v * w.w;
    }
    *(float4*)(xhat + ((size_t)row << 10) + c) = acc;
}

// ---------------------------------------------------------------------------
// active = mean_n ( count_k(top-k val > 0) ) — parallel deterministic version
// ---------------------------------------------------------------------------
__global__ void active_part(const float* __restrict__ tvg, int* __restrict__ part)
{
    __shared__ int sc[256];
    const int tid = threadIdx.x;
    int c = 0;
    for (int i = blockIdx.x * 256 + tid; i < NROWS * TOPK; i += 64 * 256)
        c += (tvg[i] > 0.0f) ? 1 : 0;
    sc[tid] = c;
    __syncthreads();
    for (int o = 128; o; o >>= 1) {
        if (tid < o) sc[tid] += sc[tid + o];
        __syncthreads();
    }
    if (tid == 0) part[blockIdx.x] = sc[0];
}

__global__ void active_fin(const int* __restrict__ part, float* __restrict__ act)
{
    if (threadIdx.x == 0) {
        int s = 0;
#pragma unroll
        for (int i = 0; i < 64; ++i) s += part[i];
        act[0] = (float)s / (float)NROWS;
    }
}

// ---------------------------------------------------------------------------
// Launch
// ---------------------------------------------------------------------------
extern "C" void kernel_launch(void* const* d_in, const int* in_sizes, int n_in,
                              void* d_out, int out_size)
{
    (void)in_sizes; (void)n_in;
    const float* x  = (const float*)d_in[0];
    const float* We = (const float*)d_in[1];
    const float* Wd = (const float*)d_in[2];
    float* out = (float*)d_out;

    __half *g_xh, *g_wh, *g_wl;
    cudaGetSymbolAddress((void**)&g_xh, g_xhi);
    cudaGetSymbolAddress((void**)&g_wh, g_whi);
    cudaGetSymbolAddress((void**)&g_wl, g_wlo);
    float* g_wt;  cudaGetSymbolAddress((void**)&g_wt,  g_wdecT);
    float* g_tvp; cudaGetSymbolAddress((void**)&g_tvp, g_tv);
    int*   g_tip; cudaGetSymbolAddress((void**)&g_tip, g_ti);
    float* g_cvp; cudaGetSymbolAddress((void**)&g_cvp, g_cv);
    int*   g_cip; cudaGetSymbolAddress((void**)&g_cip, g_ci);
    float* g_thp; cudaGetSymbolAddress((void**)&g_thp, g_thr);
    float* g_cdvp; cudaGetSymbolAddress((void**)&g_cdvp, g_cdv);
    int*   g_cdip; cudaGetSymbolAddress((void**)&g_cdip, g_cdi);
    int*   g_ccp; cudaGetSymbolAddress((void**)&g_ccp, g_ccnt);
    int*   g_flp; cudaGetSymbolAddress((void**)&g_flp, g_flag);
    int*   g_app; cudaGetSymbolAddress((void**)&g_app, g_actp);
    float* g_zp;  cudaGetSymbolAddress((void**)&g_zp,  g_zfb);

    const long long XH = (long long)NROWS * DIN;        // 8388608
    const long long ZZ = (long long)NROWS * DHID;       // 134217728
    const long long os = (long long)out_size;

    // Output layout: [x_hat | z_sparse | z | active] flat concat.
    float* xhat = out;
    float* zsp  = nullptr;
    float* z    = nullptr;
    float* act  = nullptr;
    if (os >= XH + 2 * ZZ) {
        zsp = out + XH;
        z   = out + XH + ZZ;
        if (os > XH + 2 * ZZ) act = out + XH + 2 * ZZ;
    } else if (os >= XH + ZZ) {
        zsp = out + XH;
    }
    if (!z) z = g_zp;

    cudaFuncSetAttribute(enc_gemm_hmma,
                         cudaFuncAttributeMaxDynamicSharedMemorySize, G_SMEM);
    cudaFuncSetAttribute(fallback_kernel,
                         cudaFuncAttributeMaxDynamicSharedMemorySize, DHID * 4);

    // 0. zero per-launch metadata (counters + flags)
    zero_meta_kernel<<<1, 256>>>(g_ccp, g_flp);

    // 1. fp16 splits (X: hi only; W_enc: hi+lo); per-row thresholds
    splitx_kernel<<<(NROWS * DIN / 4 + 255) / 256, 256>>>(x, g_xh, NROWS * DIN / 4);
    splitw_kernel<<<(DHID * DIN / 4 + 255) / 256, 256>>>(We, g_wh, g_wl, DHID * DIN / 4);
    thr_kernel<<<NROWS / 8, 256>>>(x, g_thp);

    // 2. transpose W_dec (independent; needed by decoder)
    transpose_kernel<<<dim3(DHID / 32, DIN / 32), dim3(32, 8)>>>(Wd, g_wt);

    // 3. HMMA encoder GEMM (2-pass fp16) + relu -> z, with fused candidate filter
    enc_gemm_hmma<<<dim3(DHID / BN, NROWS / BM), 256, G_SMEM>>>(
        g_xh, g_wh, g_wl, g_thp, z, g_cdvp, g_cdip, g_ccp);

    // 4. zero-fill z_sparse (scatter happens in refine)
    if (zsp)
        zsp_zero_kernel<<<(int)(ZZ / 4 / 256), 256>>>((float4*)zsp);

    // 5. exact top-NCAND among filtered candidates; flag anomalies
    rank_kernel<<<NROWS, 256>>>(g_cdvp, g_cdip, g_ccp, g_flp, g_cvp, g_cip);

    // 6. fallback full-row scan for flagged rows (normally instant no-op)
    fallback_kernel<<<NROWS, 256, DHID * 4>>>(z, g_flp, g_cvp, g_cip);

    // 7. exact fp64 re-rank of candidates -> true top-32, scatter z_sparse
    refine_kernel<<<NROWS, 256>>>(x, We, g_cvp, g_cip,
                                  zsp ? zsp : z, g_tvp, g_tip,
                                  zsp != nullptr ? 1 : 0);

    // 8. sparse decoder -> x_hat
    dec_kernel<<<NROWS, 256>>>(g_wt, g_tvp, g_tip, xhat);

    // 9. active scalar (parallel, deterministic int counts)
    if (act) {
        active_part<<<64, 256>>>(g_tvp, g_app);
        active_fin<<<1, 32>>>(g_app, act);
    }
}